// round 10
// baseline (speedup 1.0000x reference)
#include <cuda_runtime.h>
#include <cuda_fp16.h>
#include <math.h>

#define BATCH 128
#define OUT   256
#define MB    8      // M branches
#define INS   512    // inner size
#define TI    16     // batch tile
#define TB    16     // out tile
#define KC    256    // k chunk (f16 smem) -> 16.9KB/CTA
#define KP    (KC + 8)
#define NGRP  (BATCH / TI)       // 8 i0-groups
#define CPG   ((OUT / TB) * MB)  // 128 CTAs per group

// scratch: S[i][b][j] = sum_k sigmoid(x[i,j,k]*W[b,j,k])
__device__ float g_S[BATCH * OUT * MB];
__device__ int   g_cnt[NGRP];   // zero-init; self-resetting each launch

__device__ __forceinline__ __half2 tanh_h2(__half2 v) {
    unsigned r, a = *(unsigned*)&v;
    asm("tanh.approx.f16x2 %0, %1;" : "=r"(r) : "r"(a));
    return *(__half2*)&r;
}

// Fused: S-tile compute + last-CTA-per-group row normalize.
// __launch_bounds__(256, 8): cap 32 regs/thread -> 8 CTAs/SM -> 1184 slots
// -> ALL 1024 CTAs resident in a single wave (round 9 was reg-limited to 5).
__global__ __launch_bounds__(256, 8) void dnm_fused_kernel(
    const float* __restrict__ x,
    const float* __restrict__ w,
    float* __restrict__ out)
{
    __shared__ __half xs[TI][KP];
    __shared__ __half ws[TB][KP];
    __shared__ int s_last;

    const int tid = threadIdx.x;
    const int tx  = tid & 15;
    const int ty  = tid >> 4;
    const int grp = blockIdx.x;        // i0 group, 0..7
    const int i0  = grp * TI;
    const int b0  = blockIdx.y * TB;
    const int j   = blockIdx.z;        // 1024 CTAs total

    float acc0 = 0.0f, acc1 = 0.0f;

    #pragma unroll 1
    for (int kc = 0; kc < INS; kc += KC) {
        // ---- cooperative load + f32->f16 convert (x scaled by 0.5) ----
        #pragma unroll
        for (int it = 0; it < (TI * KC) / (4 * 256); ++it) {   // 4 iters
            int idx = it * 256 + tid;
            int r = idx >> 6, c = (idx & 63) << 2;             // 64 float4 per row
            float4 v = *(const float4*)&x[((size_t)(i0 + r) * MB + j) * INS + kc + c];
            *(__half2*)&xs[r][c]     = __floats2half2_rn(0.5f * v.x, 0.5f * v.y);
            *(__half2*)&xs[r][c + 2] = __floats2half2_rn(0.5f * v.z, 0.5f * v.w);
        }
        #pragma unroll
        for (int it = 0; it < (TB * KC) / (4 * 256); ++it) {
            int idx = it * 256 + tid;
            int r = idx >> 6, c = (idx & 63) << 2;
            float4 v = *(const float4*)&w[((size_t)(b0 + r) * MB + j) * INS + kc + c];
            *(__half2*)&ws[r][c]     = __floats2half2_rn(v.x, v.y);
            *(__half2*)&ws[r][c + 2] = __floats2half2_rn(v.z, v.w);
        }
        __syncthreads();

        // ---- main loop: 4 elements / lane / iter ----
        const __half* xr = &xs[tx][0];
        const __half* wr = &ws[ty][0];
        #pragma unroll 8
        for (int k = 0; k < KC; k += 4) {
            uint2 xv = *(const uint2*)&xr[k];
            uint2 wv = *(const uint2*)&wr[k];
            __half2 t01 = __hmul2(*(__half2*)&xv.x, *(__half2*)&wv.x);
            __half2 t23 = __hmul2(*(__half2*)&xv.y, *(__half2*)&wv.y);
            __half2 h01 = tanh_h2(t01);
            __half2 h23 = tanh_h2(t23);
            __half2 s   = __hadd2(h01, h23);
            acc0 += __low2float(s);
            acc1 += __high2float(s);
        }
        __syncthreads();
    }

    float S = fmaf(0.5f, acc0 + acc1, 0.5f * (float)INS);
    g_S[((size_t)(i0 + tx) * OUT + (b0 + ty)) * MB + j] = S;

    // ---- completion: last CTA of the i0-group normalizes its 16 rows ----
    __threadfence();
    __syncthreads();
    if (tid == 0)
        s_last = (atomicAdd(&g_cnt[grp], 1) == CPG - 1) ? 1 : 0;
    __syncthreads();
    if (!s_last) return;

    __threadfence();   // acquire side

    const int warp = tid >> 5;
    const int lane = tid & 31;

    #pragma unroll 1
    for (int rr = 0; rr < 2; ++rr) {
        const int row = i0 + 2 * warp + rr;
        float vs[8];
        float s1 = 0.0f, s2 = 0.0f;
        #pragma unroll
        for (int q = 0; q < 8; ++q) {
            int b = lane + 32 * q;
            const float4* sp = (const float4*)&g_S[((size_t)row * OUT + b) * MB];
            float4 a = __ldcg(sp);
            float4 c = __ldcg(sp + 1);
            float v = ((a.x * a.y) * (a.z * a.w)) * ((c.x * c.y) * (c.z * c.w));
            // v ~ 256^8 = 2^64 -> scale before squaring (stats scale-invariant)
            float vsc = v * 0x1p-64f;
            vs[q] = vsc;
            s1 += vsc;
            s2 += vsc * vsc;
        }
        #pragma unroll
        for (int off = 16; off > 0; off >>= 1) {
            s1 += __shfl_xor_sync(0xffffffffu, s1, off);
            s2 += __shfl_xor_sync(0xffffffffu, s2, off);
        }
        // zn = vs/total: mean exactly 1/256; ddof=1 var = (sum zn^2 - 1/256)/255
        float inv = 1.0f / s1;
        float var = (s2 * inv * inv - 1.0f / 256.0f) * (1.0f / 255.0f);
        float rstd = rsqrtf(var);
        #pragma unroll
        for (int q = 0; q < 8; ++q) {
            int b = lane + 32 * q;
            out[(size_t)row * OUT + b] = (vs[q] * inv - 1.0f / 256.0f) * rstd;
        }
    }

    if (tid == 0) g_cnt[grp] = 0;   // self-reset for next graph replay
}

extern "C" void kernel_launch(void* const* d_in, const int* in_sizes, int n_in,
                              void* d_out, int out_size)
{
    const float* x = (const float*)d_in[0];   // (128, 8, 512)
    const float* w = (const float*)d_in[1];   // (256, 8, 512)
    float* z = (float*)d_out;                 // (128, 256)

    dim3 grid(NGRP, OUT / TB, MB);            // (8, 16, 8) = 1024 CTAs
    dnm_fused_kernel<<<grid, 256>>>(x, w, z);
}

// round 11
// speedup vs baseline: 1.0917x; 1.0917x over previous
#include <cuda_runtime.h>
#include <cuda_fp16.h>
#include <math.h>

#define BATCH 128
#define OUT   256
#define MB    8      // M branches
#define INS   512    // inner size (full K in smem, f16)
#define TI    16     // batch tile
#define TB    16     // out tile
#define KP    (INS + 8)
#define NGRP  (BATCH / TI)       // 8 i0-groups
#define CPG   ((OUT / TB) * MB)  // 128 worker CTAs per group

// scratch: S[i][b][j] = sum_k sigmoid(x[i,j,k]*W[b,j,k])
__device__ float g_S[BATCH * OUT * MB];
__device__ int   g_cnt[NGRP];   // zero-init; self-resetting each launch

__device__ __forceinline__ __half2 tanh_h2(__half2 v) {
    unsigned r, a = *(unsigned*)&v;
    asm("tanh.approx.f16x2 %0, %1;" : "=r"(r) : "r"(a));
    return *(__half2*)&r;
}

// CTA-specialized fusion: z<8 -> worker CTAs (exact r4 hot loop + 1 atomic);
// z==8,y==0 -> 8 norm CTAs that spin on the group counter then normalize.
// Norm state staged in smem so the worker branch owns the register budget.
__global__ __launch_bounds__(256) void dnm_fused_kernel(
    const float* __restrict__ x,
    const float* __restrict__ w,
    float* __restrict__ out)
{
    __shared__ __half xs[TI][KP];
    __shared__ __half ws[TB][KP];

    const int tid = threadIdx.x;
    const int grp = blockIdx.x;        // i0 group, 0..7
    const int i0  = grp * TI;

    if (blockIdx.z == 8) {
        // ---------------- norm CTA ----------------
        if (blockIdx.y != 0) return;   // 120 trivial CTAs

        if (tid == 0) {
            unsigned cnt;
            do {
                asm volatile("ld.acquire.gpu.global.b32 %0, [%1];"
                             : "=r"(cnt) : "l"(&g_cnt[grp]) : "memory");
                if (cnt < CPG) __nanosleep(128);
            } while (cnt < CPG);
        }
        __syncthreads();
        __threadfence();               // acquire side for g_S

        // warp w -> rows i0+2w, i0+2w+1 ; lane owns b = lane + 32*q
        const int warp = tid >> 5;
        const int lane = tid & 31;
        float* sv = (float*)&xs[0][0];            // 8 warps * 2 rows * 256 = 16KB

        #pragma unroll 1
        for (int rr = 0; rr < 2; ++rr) {
            const int row = i0 + 2 * warp + rr;
            float* svr = &sv[(2 * warp + rr) * OUT];
            float s1 = 0.0f, s2 = 0.0f;
            #pragma unroll
            for (int q = 0; q < 8; ++q) {
                int b = lane + 32 * q;
                const float4* sp = (const float4*)&g_S[((size_t)row * OUT + b) * MB];
                float4 a = __ldcg(sp);
                float4 c = __ldcg(sp + 1);
                float v = ((a.x * a.y) * (a.z * a.w)) * ((c.x * c.y) * (c.z * c.w));
                float vsc = v * 0x1p-64f;         // 256^8 ~ 2^64: prevent overflow
                svr[b] = vsc;                      // stage in smem (reg relief)
                s1 += vsc;
                s2 += vsc * vsc;
            }
            #pragma unroll
            for (int off = 16; off > 0; off >>= 1) {
                s1 += __shfl_xor_sync(0xffffffffu, s1, off);
                s2 += __shfl_xor_sync(0xffffffffu, s2, off);
            }
            // zn = vs/total: mean exactly 1/256; ddof=1 var = (sum zn^2 - 1/256)/255
            float inv = 1.0f / s1;
            float var = (s2 * inv * inv - 1.0f / 256.0f) * (1.0f / 255.0f);
            float rstd = rsqrtf(var);
            #pragma unroll
            for (int q = 0; q < 8; ++q) {
                int b = lane + 32 * q;
                out[(size_t)row * OUT + b] = (svr[b] * inv - 1.0f / 256.0f) * rstd;
            }
        }
        __syncthreads();
        if (tid == 0) g_cnt[grp] = 0;  // self-reset for next graph replay
        return;
    }

    // ---------------- worker CTA (exact r4 fast path) ----------------
    const int tx  = tid & 15;
    const int ty  = tid >> 4;
    const int b0  = blockIdx.y * TB;
    const int j   = blockIdx.z;        // 0..7

    #pragma unroll
    for (int it = 0; it < (TI * INS) / (4 * 256); ++it) {
        int idx = it * 256 + tid;
        int r = idx >> 7, c = (idx & 127) << 2;   // 128 float4 per row
        float4 v = *(const float4*)&x[((size_t)(i0 + r) * MB + j) * INS + c];
        *(__half2*)&xs[r][c]     = __floats2half2_rn(0.5f * v.x, 0.5f * v.y);
        *(__half2*)&xs[r][c + 2] = __floats2half2_rn(0.5f * v.z, 0.5f * v.w);
    }
    #pragma unroll
    for (int it = 0; it < (TB * INS) / (4 * 256); ++it) {
        int idx = it * 256 + tid;
        int r = idx >> 7, c = (idx & 127) << 2;
        float4 v = *(const float4*)&w[((size_t)(b0 + r) * MB + j) * INS + c];
        *(__half2*)&ws[r][c]     = __floats2half2_rn(v.x, v.y);
        *(__half2*)&ws[r][c + 2] = __floats2half2_rn(v.z, v.w);
    }
    __syncthreads();

    float acc0 = 0.0f, acc1 = 0.0f;
    const __half* xr = &xs[tx][0];
    const __half* wr = &ws[ty][0];

    #pragma unroll 16
    for (int k = 0; k < INS; k += 4) {
        uint2 xv = *(const uint2*)&xr[k];
        uint2 wv = *(const uint2*)&wr[k];
        __half2 t01 = __hmul2(*(__half2*)&xv.x, *(__half2*)&wv.x);
        __half2 t23 = __hmul2(*(__half2*)&xv.y, *(__half2*)&wv.y);
        __half2 h01 = tanh_h2(t01);
        __half2 h23 = tanh_h2(t23);
        __half2 s   = __hadd2(h01, h23);
        acc0 += __low2float(s);
        acc1 += __high2float(s);
    }

    float S = fmaf(0.5f, acc0 + acc1, 0.5f * (float)INS);
    g_S[((size_t)(i0 + tx) * OUT + (b0 + ty)) * MB + j] = S;

    // release: make S visible, then signal group completion
    __threadfence();
    __syncthreads();
    if (tid == 0) atomicAdd(&g_cnt[grp], 1);
}

extern "C" void kernel_launch(void* const* d_in, const int* in_sizes, int n_in,
                              void* d_out, int out_size)
{
    const float* x = (const float*)d_in[0];   // (128, 8, 512)
    const float* w = (const float*)d_in[1];   // (256, 8, 512)
    float* z = (float*)d_out;                 // (128, 256)

    dim3 grid(NGRP, OUT / TB, MB + 1);        // (8, 16, 9): z<8 work, z=8 norm
    dnm_fused_kernel<<<grid, 256>>>(x, w, z);
}